// round 2
// baseline (speedup 1.0000x reference)
#include <cuda_runtime.h>
#include <cstdint>

#define Bb 8
#define Ss 2048
#define Dd 1024
#define Mtot (Bb * Ss)

// Scratch (device globals: no allocation in kernel_launch)
__device__ float g_q[(size_t)Mtot * Dd];   // 64 MB
__device__ float g_k[(size_t)Mtot * Dd];   // 64 MB
__device__ float g_w[Mtot];                // v_t . Wo per token
__device__ float g_u[Dd];                  // Wv @ Wo
__device__ float g_c;                      // bv . Wo

#define NEG_INF (-1e30f)

// ---------------------------------------------------------------------------
// prep: u = Wv @ Wo  (row-dot), c = bv . Wo
// ---------------------------------------------------------------------------
__global__ void prep_u(const float* __restrict__ Wv, const float* __restrict__ Wo)
{
    int d = blockIdx.x * 256 + threadIdx.x;
    const float4* wr = (const float4*)(Wv + (size_t)d * Dd);
    const float4* wo = (const float4*)Wo;
    float s = 0.f;
    #pragma unroll 4
    for (int j = 0; j < Dd / 4; ++j) {
        float4 a = wr[j], b = wo[j];
        s += a.x * b.x + a.y * b.y + a.z * b.z + a.w * b.w;
    }
    g_u[d] = s;
}

__global__ void prep_c(const float* __restrict__ bv, const float* __restrict__ Wo)
{
    __shared__ float red[8];
    int tid = threadIdx.x;
    float4 a = ((const float4*)bv)[tid];
    float4 b = ((const float4*)Wo)[tid];
    float s = a.x * b.x + a.y * b.y + a.z * b.z + a.w * b.w;
    #pragma unroll
    for (int off = 16; off; off >>= 1) s += __shfl_xor_sync(0xffffffffu, s, off);
    if ((tid & 31) == 0) red[tid >> 5] = s;
    __syncthreads();
    if (tid < 8) {
        s = red[tid];
        #pragma unroll
        for (int off = 4; off; off >>= 1) s += __shfl_xor_sync(0xffu, s, off);
        if (tid == 0) g_c = s;
    }
}

// ---------------------------------------------------------------------------
// w[m] = x[m,:] . u + c   (one 256-thread block per row)
// ---------------------------------------------------------------------------
__global__ void gemv_w(const float* __restrict__ x)
{
    __shared__ float red[8];
    int m = blockIdx.x;
    int tid = threadIdx.x;
    const float4* xr = (const float4*)(x + (size_t)m * Dd);
    const float4* ur = (const float4*)g_u;
    float4 a = xr[tid], u = ur[tid];
    float s = a.x * u.x + a.y * u.y + a.z * u.z + a.w * u.w;
    #pragma unroll
    for (int off = 16; off; off >>= 1) s += __shfl_xor_sync(0xffffffffu, s, off);
    if ((tid & 31) == 0) red[tid >> 5] = s;
    __syncthreads();
    if (tid < 8) {
        s = red[tid];
        #pragma unroll
        for (int off = 4; off; off >>= 1) s += __shfl_xor_sync(0xffu, s, off);
        if (tid == 0) g_w[m] = s + g_c;
    }
}

// ---------------------------------------------------------------------------
// SGEMM: C[M, D] = A[M, D] @ W[D, D] + bias   (128x128x16 tiles, 8x8/thread,
// double-buffered smem). target: 0 -> g_q, 1 -> g_k.
// ---------------------------------------------------------------------------
__global__ void __launch_bounds__(256, 2)
sgemm_bias(const float* __restrict__ A, const float* __restrict__ W,
           const float* __restrict__ bias, int target)
{
    __shared__ float As[2][16][132];   // transposed A tile, padded
    __shared__ float Bs[2][16][132];   // W tile, padded

    float* C = (target == 0) ? g_q : g_k;

    const int K = Dd, N = Dd;
    int tid = threadIdx.x;
    int m0 = blockIdx.y * 128;
    int n0 = blockIdx.x * 128;

    int ar = tid >> 2;             // 0..63
    int ac = (tid & 3) << 2;       // 0,4,8,12
    int br = tid >> 5;             // 0..7
    int bc = (tid & 31) << 2;      // 0..124

    const float* Aptr = A + (size_t)(m0 + ar) * K + ac;
    const float* Wptr = W + (size_t)br * N + n0 + bc;

    float4 a0 = *(const float4*)(Aptr);
    float4 a1 = *(const float4*)(Aptr + (size_t)64 * K);
    float4 b0 = *(const float4*)(Wptr);
    float4 b1 = *(const float4*)(Wptr + (size_t)8 * N);

    As[0][ac + 0][ar] = a0.x; As[0][ac + 1][ar] = a0.y;
    As[0][ac + 2][ar] = a0.z; As[0][ac + 3][ar] = a0.w;
    As[0][ac + 0][ar + 64] = a1.x; As[0][ac + 1][ar + 64] = a1.y;
    As[0][ac + 2][ar + 64] = a1.z; As[0][ac + 3][ar + 64] = a1.w;
    *(float4*)&Bs[0][br][bc] = b0;
    *(float4*)&Bs[0][br + 8][bc] = b1;
    __syncthreads();

    int tx = tid & 15, ty = tid >> 4;
    float acc[8][8] = {};

    const int NK = K / 16;
    for (int kt = 0; kt < NK; ++kt) {
        int cur = kt & 1, nxt = cur ^ 1;
        if (kt + 1 < NK) {
            const float* Ap = Aptr + (kt + 1) * 16;
            a0 = *(const float4*)(Ap);
            a1 = *(const float4*)(Ap + (size_t)64 * K);
            const float* Wp = Wptr + (size_t)(kt + 1) * 16 * N;
            b0 = *(const float4*)(Wp);
            b1 = *(const float4*)(Wp + (size_t)8 * N);
        }
        #pragma unroll
        for (int kk = 0; kk < 16; ++kk) {
            float ra[8], rb[8];
            *(float4*)&ra[0] = *(const float4*)&As[cur][kk][ty * 8];
            *(float4*)&ra[4] = *(const float4*)&As[cur][kk][ty * 8 + 4];
            *(float4*)&rb[0] = *(const float4*)&Bs[cur][kk][tx * 8];
            *(float4*)&rb[4] = *(const float4*)&Bs[cur][kk][tx * 8 + 4];
            #pragma unroll
            for (int i = 0; i < 8; ++i)
                #pragma unroll
                for (int j = 0; j < 8; ++j)
                    acc[i][j] += ra[i] * rb[j];
        }
        if (kt + 1 < NK) {
            As[nxt][ac + 0][ar] = a0.x; As[nxt][ac + 1][ar] = a0.y;
            As[nxt][ac + 2][ar] = a0.z; As[nxt][ac + 3][ar] = a0.w;
            As[nxt][ac + 0][ar + 64] = a1.x; As[nxt][ac + 1][ar + 64] = a1.y;
            As[nxt][ac + 2][ar + 64] = a1.z; As[nxt][ac + 3][ar + 64] = a1.w;
            *(float4*)&Bs[nxt][br][bc] = b0;
            *(float4*)&Bs[nxt][br + 8][bc] = b1;
        }
        __syncthreads();
    }

    float4 bz0 = *(const float4*)(bias + n0 + tx * 8);
    float4 bz1 = *(const float4*)(bias + n0 + tx * 8 + 4);
    #pragma unroll
    for (int i = 0; i < 8; ++i) {
        size_t m = (size_t)(m0 + ty * 8 + i);
        float* Cr = C + m * N + n0 + tx * 8;
        float4 o0, o1;
        o0.x = acc[i][0] + bz0.x; o0.y = acc[i][1] + bz0.y;
        o0.z = acc[i][2] + bz0.z; o0.w = acc[i][3] + bz0.w;
        o1.x = acc[i][4] + bz1.x; o1.y = acc[i][5] + bz1.y;
        o1.z = acc[i][6] + bz1.z; o1.w = acc[i][7] + bz1.w;
        *(float4*)Cr = o0;
        *(float4*)(Cr + 4) = o1;
    }
}

// ---------------------------------------------------------------------------
// Flash-style fused scores + online softmax + w-weighted reduction.
// One CTA = 64 q-rows of one batch. Tiles of 128 t-columns, K-dim streamed
// in chunks of 16 with double buffering. Per-row state (m, l, sum p*w) only.
// Thread layout 16x16, 4 rows x 8 cols per thread.
// ---------------------------------------------------------------------------
__global__ void __launch_bounds__(256, 2)
flash_attn(const float* __restrict__ bo, float* __restrict__ out)
{
    __shared__ float Qs[2][16][68];
    __shared__ float Ks[2][16][132];

    int b = blockIdx.y;
    int q0 = blockIdx.x * 64;
    int tid = threadIdx.x;
    int tx = tid & 15, ty = tid >> 4;

    const float* qbase = g_q + ((size_t)b * Ss + q0) * Dd;
    const float* kbase = g_k + (size_t)b * Ss * Dd;

    int ar = tid >> 2;          // 0..63
    int ac = (tid & 3) << 2;    // 0,4,8,12

    float rm[4], rl[4], racc[4];
    #pragma unroll
    for (int i = 0; i < 4; ++i) { rm[i] = NEG_INF; rl[i] = 0.f; racc[i] = 0.f; }

    const float bo0 = bo[0];
    const float* qp = qbase + (size_t)ar * Dd + ac;

    for (int t0 = 0; t0 < Ss; t0 += 128) {
        const float* ktile = kbase + (size_t)t0 * Dd;
        const float* kp0 = ktile + (size_t)ar * Dd + ac;
        const float* kp1 = ktile + (size_t)(ar + 64) * Dd + ac;

        // w values for my 8 columns
        float rw[8];
        {
            const float4* wp = (const float4*)(g_w + (size_t)b * Ss + t0 + tx * 8);
            float4 w0 = wp[0], w1 = wp[1];
            rw[0] = w0.x; rw[1] = w0.y; rw[2] = w0.z; rw[3] = w0.w;
            rw[4] = w1.x; rw[5] = w1.y; rw[6] = w1.z; rw[7] = w1.w;
        }

        float acc[4][8] = {};

        float4 qa = *(const float4*)(qp);
        float4 ka = *(const float4*)(kp0);
        float4 kb = *(const float4*)(kp1);
        Qs[0][ac + 0][ar] = qa.x; Qs[0][ac + 1][ar] = qa.y;
        Qs[0][ac + 2][ar] = qa.z; Qs[0][ac + 3][ar] = qa.w;
        Ks[0][ac + 0][ar] = ka.x; Ks[0][ac + 1][ar] = ka.y;
        Ks[0][ac + 2][ar] = ka.z; Ks[0][ac + 3][ar] = ka.w;
        Ks[0][ac + 0][ar + 64] = kb.x; Ks[0][ac + 1][ar + 64] = kb.y;
        Ks[0][ac + 2][ar + 64] = kb.z; Ks[0][ac + 3][ar + 64] = kb.w;
        __syncthreads();

        for (int kt = 0; kt < Dd / 16; ++kt) {
            int cur = kt & 1, nxt = cur ^ 1;
            if (kt + 1 < Dd / 16) {
                qa = *(const float4*)(qp + (kt + 1) * 16);
                ka = *(const float4*)(kp0 + (kt + 1) * 16);
                kb = *(const float4*)(kp1 + (kt + 1) * 16);
            }
            #pragma unroll
            for (int kk = 0; kk < 16; ++kk) {
                float rq[4], rk[8];
                rq[0] = Qs[cur][kk][ty * 4 + 0];
                rq[1] = Qs[cur][kk][ty * 4 + 1];
                rq[2] = Qs[cur][kk][ty * 4 + 2];
                rq[3] = Qs[cur][kk][ty * 4 + 3];
                *(float4*)&rk[0] = *(const float4*)&Ks[cur][kk][tx * 8];
                *(float4*)&rk[4] = *(const float4*)&Ks[cur][kk][tx * 8 + 4];
                #pragma unroll
                for (int i = 0; i < 4; ++i)
                    #pragma unroll
                    for (int j = 0; j < 8; ++j)
                        acc[i][j] += rq[i] * rk[j];
            }
            if (kt + 1 < Dd / 16) {
                qa.x += 0.f;  // keep compiler from reordering nothing; harmless
                Qs[nxt][ac + 0][ar] = qa.x; Qs[nxt][ac + 1][ar] = qa.y;
                Qs[nxt][ac + 2][ar] = qa.z; Qs[nxt][ac + 3][ar] = qa.w;
                Ks[nxt][ac + 0][ar] = ka.x; Ks[nxt][ac + 1][ar] = ka.y;
                Ks[nxt][ac + 2][ar] = ka.z; Ks[nxt][ac + 3][ar] = ka.w;
                Ks[nxt][ac + 0][ar + 64] = kb.x; Ks[nxt][ac + 1][ar + 64] = kb.y;
                Ks[nxt][ac + 2][ar + 64] = kb.z; Ks[nxt][ac + 3][ar + 64] = kb.w;
            }
            __syncthreads();
        }

        // online softmax update (row stats replicated across the 16 tx lanes)
        #pragma unroll
        for (int i = 0; i < 4; ++i) {
            float tm = acc[i][0];
            #pragma unroll
            for (int j = 1; j < 8; ++j) tm = fmaxf(tm, acc[i][j]);
            #pragma unroll
            for (int off = 8; off; off >>= 1)
                tm = fmaxf(tm, __shfl_xor_sync(0xffffffffu, tm, off));
            float nm = fmaxf(rm[i], tm);
            float tl = 0.f, ta = 0.f;
            #pragma unroll
            for (int j = 0; j < 8; ++j) {
                float p = __expf(acc[i][j] - nm);
                tl += p;
                ta += p * rw[j];
            }
            #pragma unroll
            for (int off = 8; off; off >>= 1) {
                tl += __shfl_xor_sync(0xffffffffu, tl, off);
                ta += __shfl_xor_sync(0xffffffffu, ta, off);
            }
            float f = __expf(rm[i] - nm);
            rl[i] = rl[i] * f + tl;
            racc[i] = racc[i] * f + ta;
            rm[i] = nm;
        }
    }

    if (tx == 0) {
        #pragma unroll
        for (int i = 0; i < 4; ++i) {
            int row = q0 + ty * 4 + i;
            out[(size_t)b * Ss + row] = racc[i] / rl[i] + bo0;
        }
    }
}

// ---------------------------------------------------------------------------
extern "C" void kernel_launch(void* const* d_in, const int* in_sizes, int n_in,
                              void* d_out, int out_size)
{
    const float* x  = (const float*)d_in[0];
    const float* Wq = (const float*)d_in[1];
    const float* bq = (const float*)d_in[2];
    const float* Wk = (const float*)d_in[3];
    const float* bk = (const float*)d_in[4];
    const float* Wv = (const float*)d_in[5];
    const float* bv = (const float*)d_in[6];
    const float* Wo = (const float*)d_in[7];
    const float* bo = (const float*)d_in[8];
    float* out = (float*)d_out;

    (void)in_sizes; (void)n_in; (void)out_size;

    // u = Wv@Wo, c = bv.Wo, w = x@u + c
    prep_u<<<Dd / 256, 256>>>(Wv, Wo);
    prep_c<<<1, 256>>>(bv, Wo);
    gemv_w<<<Mtot, 256>>>(x);

    // q = x@Wq + bq ; k = x@Wk + bk
    dim3 gg(Dd / 128, Mtot / 128);
    sgemm_bias<<<gg, 256>>>(x, Wq, bq, 0);
    sgemm_bias<<<gg, 256>>>(x, Wk, bk, 1);

    // fused scores + softmax + (sum p*w)/l + bo
    dim3 gf(Ss / 64, Bb);
    flash_attn<<<gf, 256>>>(bo, out);
}

// round 6
// speedup vs baseline: 1.6865x; 1.6865x over previous
#include <cuda_runtime.h>
#include <cuda_bf16.h>
#include <mma.h>
#include <cstdint>

using namespace nvcuda;

#define Bb 8
#define Ss 2048
#define Dd 1024
#define Mtot (Bb * Ss)

// ---------------------------------------------------------------------------
// Device-global scratch (no allocations allowed) — fp32 only (round-2 layout)
// ---------------------------------------------------------------------------
__device__ float g_q[(size_t)Mtot * Dd];   // 64 MB
__device__ float g_k[(size_t)Mtot * Dd];   // 64 MB
__device__ float g_w[Mtot];                // v_t . Wo per token
__device__ float g_u[Dd];                  // Wv @ Wo
__device__ float g_c;                      // bv . Wo

// ---------------------------------------------------------------------------
// prep: u = Wv @ Wo  (row-dot), c = bv . Wo      [validated round 2]
// ---------------------------------------------------------------------------
__global__ void prep_u(const float* __restrict__ Wv, const float* __restrict__ Wo)
{
    int d = blockIdx.x * 256 + threadIdx.x;
    const float4* wr = (const float4*)(Wv + (size_t)d * Dd);
    const float4* wo = (const float4*)Wo;
    float s = 0.f;
    #pragma unroll 4
    for (int j = 0; j < Dd / 4; ++j) {
        float4 a = wr[j], b = wo[j];
        s += a.x * b.x + a.y * b.y + a.z * b.z + a.w * b.w;
    }
    g_u[d] = s;
}

__global__ void prep_c(const float* __restrict__ bv, const float* __restrict__ Wo)
{
    __shared__ float red[8];
    int tid = threadIdx.x;
    float4 a = ((const float4*)bv)[tid];
    float4 b = ((const float4*)Wo)[tid];
    float s = a.x * b.x + a.y * b.y + a.z * b.z + a.w * b.w;
    #pragma unroll
    for (int off = 16; off; off >>= 1) s += __shfl_xor_sync(0xffffffffu, s, off);
    if ((tid & 31) == 0) red[tid >> 5] = s;
    __syncthreads();
    if (tid < 8) {
        s = red[tid];
        #pragma unroll
        for (int off = 4; off; off >>= 1) s += __shfl_xor_sync(0xffu, s, off);
        if (tid == 0) g_c = s;
    }
}

__global__ void gemv_w(const float* __restrict__ x)
{
    __shared__ float red[8];
    int m = blockIdx.x;
    int tid = threadIdx.x;
    const float4* xr = (const float4*)(x + (size_t)m * Dd);
    const float4* ur = (const float4*)g_u;
    float4 a = xr[tid], u = ur[tid];
    float s = a.x * u.x + a.y * u.y + a.z * u.z + a.w * u.w;
    #pragma unroll
    for (int off = 16; off; off >>= 1) s += __shfl_xor_sync(0xffffffffu, s, off);
    if ((tid & 31) == 0) red[tid >> 5] = s;
    __syncthreads();
    if (tid < 8) {
        s = red[tid];
        #pragma unroll
        for (int off = 4; off; off >>= 1) s += __shfl_xor_sync(0xffu, s, off);
        if (tid == 0) g_w[m] = s + g_c;
    }
}

// ---------------------------------------------------------------------------
// SGEMM: C[M, D] = A[M, D] @ W[D, D] + bias     [validated round 2, verbatim]
// ---------------------------------------------------------------------------
__global__ void __launch_bounds__(256, 2)
sgemm_bias(const float* __restrict__ A, const float* __restrict__ W,
           const float* __restrict__ bias, int target)
{
    __shared__ float As[2][16][132];
    __shared__ float Bs[2][16][132];

    float* C = (target == 0) ? g_q : g_k;

    const int K = Dd, N = Dd;
    int tid = threadIdx.x;
    int m0 = blockIdx.y * 128;
    int n0 = blockIdx.x * 128;

    int ar = tid >> 2;
    int ac = (tid & 3) << 2;
    int br = tid >> 5;
    int bc = (tid & 31) << 2;

    const float* Aptr = A + (size_t)(m0 + ar) * K + ac;
    const float* Wptr = W + (size_t)br * N + n0 + bc;

    float4 a0 = *(const float4*)(Aptr);
    float4 a1 = *(const float4*)(Aptr + (size_t)64 * K);
    float4 b0 = *(const float4*)(Wptr);
    float4 b1 = *(const float4*)(Wptr + (size_t)8 * N);

    As[0][ac + 0][ar] = a0.x; As[0][ac + 1][ar] = a0.y;
    As[0][ac + 2][ar] = a0.z; As[0][ac + 3][ar] = a0.w;
    As[0][ac + 0][ar + 64] = a1.x; As[0][ac + 1][ar + 64] = a1.y;
    As[0][ac + 2][ar + 64] = a1.z; As[0][ac + 3][ar + 64] = a1.w;
    *(float4*)&Bs[0][br][bc] = b0;
    *(float4*)&Bs[0][br + 8][bc] = b1;
    __syncthreads();

    int tx = tid & 15, ty = tid >> 4;
    float acc[8][8] = {};

    const int NK = K / 16;
    for (int kt = 0; kt < NK; ++kt) {
        int cur = kt & 1, nxt = cur ^ 1;
        if (kt + 1 < NK) {
            const float* Ap = Aptr + (kt + 1) * 16;
            a0 = *(const float4*)(Ap);
            a1 = *(const float4*)(Ap + (size_t)64 * K);
            const float* Wp = Wptr + (size_t)(kt + 1) * 16 * N;
            b0 = *(const float4*)(Wp);
            b1 = *(const float4*)(Wp + (size_t)8 * N);
        }
        #pragma unroll
        for (int kk = 0; kk < 16; ++kk) {
            float ra[8], rb[8];
            *(float4*)&ra[0] = *(const float4*)&As[cur][kk][ty * 8];
            *(float4*)&ra[4] = *(const float4*)&As[cur][kk][ty * 8 + 4];
            *(float4*)&rb[0] = *(const float4*)&Bs[cur][kk][tx * 8];
            *(float4*)&rb[4] = *(const float4*)&Bs[cur][kk][tx * 8 + 4];
            #pragma unroll
            for (int i = 0; i < 8; ++i)
                #pragma unroll
                for (int j = 0; j < 8; ++j)
                    acc[i][j] += ra[i] * rb[j];
        }
        if (kt + 1 < NK) {
            As[nxt][ac + 0][ar] = a0.x; As[nxt][ac + 1][ar] = a0.y;
            As[nxt][ac + 2][ar] = a0.z; As[nxt][ac + 3][ar] = a0.w;
            As[nxt][ac + 0][ar + 64] = a1.x; As[nxt][ac + 1][ar + 64] = a1.y;
            As[nxt][ac + 2][ar + 64] = a1.z; As[nxt][ac + 3][ar + 64] = a1.w;
            *(float4*)&Bs[nxt][br][bc] = b0;
            *(float4*)&Bs[nxt][br + 8][bc] = b1;
        }
        __syncthreads();
    }

    float4 bz0 = *(const float4*)(bias + n0 + tx * 8);
    float4 bz1 = *(const float4*)(bias + n0 + tx * 8 + 4);
    #pragma unroll
    for (int i = 0; i < 8; ++i) {
        size_t m = (size_t)(m0 + ty * 8 + i);
        float* Cr = C + m * N + n0 + tx * 8;
        float4 o0, o1;
        o0.x = acc[i][0] + bz0.x; o0.y = acc[i][1] + bz0.y;
        o0.z = acc[i][2] + bz0.z; o0.w = acc[i][3] + bz0.w;
        o1.x = acc[i][4] + bz1.x; o1.y = acc[i][5] + bz1.y;
        o1.z = acc[i][6] + bz1.z; o1.w = acc[i][7] + bz1.w;
        *(float4*)Cr = o0;
        *(float4*)(Cr + 4) = o1;
    }
}

// ---------------------------------------------------------------------------
// WMMA flash (new this round): fp32 q/k loaded with plain loads, hi/lo split
// in registers, 3-split bf16 wmma scores, smem-staged softmax + rank-1 w.
// grid (Ss/128, Bb), 256 threads = 8 warps (warp tile 32m x 64n).
// ---------------------------------------------------------------------------
#define FTILE_E 40                    // smem tile pitch, elements
#define FTILE_B (128 * 80)            // 10240 bytes per 128x32 bf16 tile
#define FBUF_B  (4 * FTILE_B)         // Qhi,Qlo,Khi,Klo
#define FBUFS   (2 * FBUF_B)          // 81920, double buffered
#define FL_WS   FBUFS                 // 128 f32 w values
#define FLASH_SMEM (FL_WS + 512)      // 82432
#define STG_PITCH 132                 // score stage (aliases dead buffers)

typedef wmma::fragment<wmma::matrix_a, 16, 16, 16, __nv_bfloat16, wmma::row_major> FragA;
typedef wmma::fragment<wmma::matrix_b, 16, 16, 16, __nv_bfloat16, wmma::col_major> FragB;
typedef wmma::fragment<wmma::accumulator, 16, 16, 16, float> FragC;

__device__ __forceinline__ void load16(float* v, const float* p) {
#pragma unroll
    for (int i = 0; i < 4; ++i) ((float4*)v)[i] = ((const float4*)p)[i];
}

// Split 16 floats to bf16 hi/lo and store 32B to each tile at byte offset off.
__device__ __forceinline__ void split16_store(char* hi, char* lo, uint32_t off,
                                              const float* v) {
    alignas(16) __nv_bfloat16 h[16], l[16];
#pragma unroll
    for (int j = 0; j < 16; ++j) {
        float f = v[j];
        __nv_bfloat16 hh = __float2bfloat16(f);
        h[j] = hh;
        l[j] = __float2bfloat16(f - __bfloat162float(hh));
    }
    *(uint4*)(hi + off)      = ((const uint4*)h)[0];
    *(uint4*)(hi + off + 16) = ((const uint4*)h)[1];
    *(uint4*)(lo + off)      = ((const uint4*)l)[0];
    *(uint4*)(lo + off + 16) = ((const uint4*)l)[1];
}

// One 32-k chunk of 3-split wmma: warp tile 32(m) x 64(n).
__device__ __forceinline__ void mma_chunk(const char* buf, int wm, int wn,
                                          FragC (&acc)[2][4])
{
    const __nv_bfloat16* tQ  = (const __nv_bfloat16*)(buf);
    const __nv_bfloat16* tQl = (const __nv_bfloat16*)(buf + FTILE_B);
    const __nv_bfloat16* tK  = (const __nv_bfloat16*)(buf + 2 * FTILE_B);
    const __nv_bfloat16* tKl = (const __nv_bfloat16*)(buf + 3 * FTILE_B);
#pragma unroll
    for (int ks = 0; ks < 2; ++ks) {
        FragA ah[2], al[2];
#pragma unroll
        for (int mi = 0; mi < 2; ++mi) {
            int ro = (32 * wm + 16 * mi) * FTILE_E + ks * 16;
            wmma::load_matrix_sync(ah[mi], tQ + ro, FTILE_E);
            wmma::load_matrix_sync(al[mi], tQl + ro, FTILE_E);
        }
#pragma unroll
        for (int p = 0; p < 4; ++p) {
            int ro = (64 * wn + 16 * p) * FTILE_E + ks * 16;
            FragB bh, bl;
            wmma::load_matrix_sync(bh, tK + ro, FTILE_E);
            wmma::load_matrix_sync(bl, tKl + ro, FTILE_E);
#pragma unroll
            for (int mi = 0; mi < 2; ++mi) {
                wmma::mma_sync(acc[mi][p], ah[mi], bh, acc[mi][p]);
                wmma::mma_sync(acc[mi][p], ah[mi], bl, acc[mi][p]);
                wmma::mma_sync(acc[mi][p], al[mi], bh, acc[mi][p]);
            }
        }
    }
}

__global__ void __launch_bounds__(256, 1)
wmma_flash(const float* __restrict__ bo, float* __restrict__ out)
{
    extern __shared__ char sm[];
    int tid = threadIdx.x;
    int wid = tid >> 5;
    int wm = wid & 3, wn = wid >> 2;
    int b = blockIdx.y;
    int q0 = blockIdx.x * 128;

    float* ws = (float*)(sm + FL_WS);
    float* stage = (float*)sm;                 // aliases dead mma buffers

    const float* qb = g_q + ((size_t)b * Ss + q0) * Dd;
    const float* kb = g_k + (size_t)b * Ss * Dd;
    const float bo0 = __ldg(bo);

    int row = tid >> 1;                        // 0..127
    int half = tid & 1;                        // 16-col half
    uint32_t soff = (uint32_t)row * 80 + half * 32;
    const float* qrow = qb + (size_t)row * Dd + half * 16;

    const int NK = Dd / 32;
    float rm = -1e30f, rl = 0.f, rc = 0.f;     // per-row state, row = tid (<128)

    for (int t0 = 0; t0 < Ss; t0 += 128) {
        const float* krow = kb + (size_t)(t0 + row) * Dd + half * 16;
        if (tid < 128) ws[tid] = g_w[(size_t)b * Ss + t0 + tid];

        FragC acc[2][4];
#pragma unroll
        for (int mi = 0; mi < 2; ++mi)
#pragma unroll
            for (int p = 0; p < 4; ++p)
                wmma::fill_fragment(acc[mi][p], 0.f);

        float qreg[16], kreg[16];

        // chunk 0 direct into buffer 0
        load16(qreg, qrow);
        load16(kreg, krow);
        split16_store(sm, sm + FTILE_B, soff, qreg);
        split16_store(sm + 2 * FTILE_B, sm + 3 * FTILE_B, soff, kreg);
        __syncthreads();

        for (int kc = 0; kc < NK; ++kc) {
            char* buf = sm + (size_t)(kc & 1) * FBUF_B;
            bool pre = (kc + 1 < NK);
            if (pre) {
                load16(qreg, qrow + (kc + 1) * 32);
                load16(kreg, krow + (kc + 1) * 32);
            }
            mma_chunk(buf, wm, wn, acc);
            if (pre) {
                char* nb = sm + (size_t)((kc + 1) & 1) * FBUF_B;
                split16_store(nb, nb + FTILE_B, soff, qreg);
                split16_store(nb + 2 * FTILE_B, nb + 3 * FTILE_B, soff, kreg);
            }
            __syncthreads();
        }

        // stage the full 128x128 fp32 score tile (buffers dead now)
#pragma unroll
        for (int mi = 0; mi < 2; ++mi)
#pragma unroll
            for (int p = 0; p < 4; ++p)
                wmma::store_matrix_sync(
                    stage + (size_t)(32 * wm + 16 * mi) * STG_PITCH + 64 * wn + 16 * p,
                    acc[mi][p], STG_PITCH, wmma::mem_row_major);
        __syncthreads();

        // per-row online softmax + rank-1 reduction (row = tid)
        if (tid < 128) {
            const float4* rp = (const float4*)(stage + (size_t)tid * STG_PITCH);
            float m = -1e30f;
#pragma unroll 8
            for (int j = 0; j < 32; ++j) {
                float4 s4 = rp[j];
                m = fmaxf(m, fmaxf(fmaxf(s4.x, s4.y), fmaxf(s4.z, s4.w)));
            }
            float nm = fmaxf(rm, m);
            float f = __expf(rm - nm);
            float tl = 0.f, ta = 0.f;
            const float4* wp = (const float4*)ws;
#pragma unroll 8
            for (int j = 0; j < 32; ++j) {
                float4 s4 = rp[j];
                float4 w4 = wp[j];
                float p0 = __expf(s4.x - nm);
                float p1 = __expf(s4.y - nm);
                float p2 = __expf(s4.z - nm);
                float p3 = __expf(s4.w - nm);
                tl += (p0 + p1) + (p2 + p3);
                ta += p0 * w4.x + p1 * w4.y + p2 * w4.z + p3 * w4.w;
            }
            rl = rl * f + tl;
            rc = rc * f + ta;
            rm = nm;
        }
        __syncthreads();   // stage free before next tile's chunk-0 stores
    }

    if (tid < 128)
        out[(size_t)b * Ss + q0 + tid] = rc / rl + bo0;
}

// ---------------------------------------------------------------------------
extern "C" void kernel_launch(void* const* d_in, const int* in_sizes, int n_in,
                              void* d_out, int out_size)
{
    const float* x  = (const float*)d_in[0];
    const float* Wq = (const float*)d_in[1];
    const float* bq = (const float*)d_in[2];
    const float* Wk = (const float*)d_in[3];
    const float* bk = (const float*)d_in[4];
    const float* Wv = (const float*)d_in[5];
    const float* bv = (const float*)d_in[6];
    const float* Wo = (const float*)d_in[7];
    const float* bo = (const float*)d_in[8];
    float* out = (float*)d_out;

    (void)in_sizes; (void)n_in; (void)out_size;

    static bool attr_done = false;
    if (!attr_done) {
        cudaFuncSetAttribute(wmma_flash,
                             cudaFuncAttributeMaxDynamicSharedMemorySize, FLASH_SMEM);
        attr_done = true;
    }

    // u = Wv@Wo, c = bv.Wo, w = x@u + c
    prep_u<<<Dd / 256, 256>>>(Wv, Wo);
    prep_c<<<1, 256>>>(bv, Wo);
    gemv_w<<<Mtot, 256>>>(x);

    // q = x@Wq + bq ; k = x@Wk + bk  (validated fp32 SGEMM)
    dim3 gg(Dd / 128, Mtot / 128);
    sgemm_bias<<<gg, 256>>>(x, Wq, bq, 0);
    sgemm_bias<<<gg, 256>>>(x, Wk, bk, 1);

    // fused scores + softmax + rank-1 reduction (wmma bf16 3-split)
    dim3 gf(Ss / 128, Bb);
    wmma_flash<<<gf, 256, FLASH_SMEM>>>(bo, out);
}

// round 7
// speedup vs baseline: 2.3429x; 1.3892x over previous
#include <cuda_runtime.h>
#include <cuda_bf16.h>
#include <mma.h>
#include <cstdint>

using namespace nvcuda;

#define Bb 8
#define Ss 2048
#define Dd 1024
#define Mtot (Bb * Ss)

// ---------------------------------------------------------------------------
// Device-global scratch
// ---------------------------------------------------------------------------
__device__ float g_y[(size_t)Mtot * Dd];   // y = x @ M   (64 MB)
__device__ float g_mt[(size_t)Dd * Dd];    // Mt = Wk @ Wq^T  (so y = x @ Mt^T)
__device__ float g_w[Mtot];                // v_t . Wo per token
__device__ float g_bt[Mtot];               // x_t . (Wk bq) score column bias
__device__ float g_u[Dd];                  // Wv @ Wo
__device__ float g_h[Dd];                  // Wk @ bq
__device__ float g_c;                      // bv . Wo

// ---------------------------------------------------------------------------
// prep: row-dot kernels (validated round 2 pattern)
// ---------------------------------------------------------------------------
__global__ void prep_dot(const float* __restrict__ Wm, const float* __restrict__ v,
                         float* __restrict__ outv)
{
    int d = blockIdx.x * 256 + threadIdx.x;
    const float4* wr = (const float4*)(Wm + (size_t)d * Dd);
    const float4* vo = (const float4*)v;
    float s = 0.f;
    #pragma unroll 4
    for (int j = 0; j < Dd / 4; ++j) {
        float4 a = wr[j], b = vo[j];
        s += a.x * b.x + a.y * b.y + a.z * b.z + a.w * b.w;
    }
    outv[d] = s;
}

__global__ void prep_c(const float* __restrict__ bv, const float* __restrict__ Wo)
{
    __shared__ float red[8];
    int tid = threadIdx.x;
    float4 a = ((const float4*)bv)[tid];
    float4 b = ((const float4*)Wo)[tid];
    float s = a.x * b.x + a.y * b.y + a.z * b.z + a.w * b.w;
    #pragma unroll
    for (int off = 16; off; off >>= 1) s += __shfl_xor_sync(0xffffffffu, s, off);
    if ((tid & 31) == 0) red[tid >> 5] = s;
    __syncthreads();
    if (tid < 8) {
        s = red[tid];
        #pragma unroll
        for (int off = 4; off; off >>= 1) s += __shfl_xor_sync(0xffu, s, off);
        if (tid == 0) g_c = s;
    }
}

// w[m] = x[m,:].u + c  /  bt[m] = x[m,:].h   (one block per row; add_c flag)
__global__ void gemv_row(const float* __restrict__ x, const float* __restrict__ vec,
                         float* __restrict__ outv, int add_c)
{
    __shared__ float red[8];
    int m = blockIdx.x;
    int tid = threadIdx.x;
    const float4* xr = (const float4*)(x + (size_t)m * Dd);
    const float4* ur = (const float4*)vec;
    float4 a = xr[tid], u = ur[tid];
    float s = a.x * u.x + a.y * u.y + a.z * u.z + a.w * u.w;
    #pragma unroll
    for (int off = 16; off; off >>= 1) s += __shfl_xor_sync(0xffffffffu, s, off);
    if ((tid & 31) == 0) red[tid >> 5] = s;
    __syncthreads();
    if (tid < 8) {
        s = red[tid];
        #pragma unroll
        for (int off = 4; off; off >>= 1) s += __shfl_xor_sync(0xffu, s, off);
        if (tid == 0) outv[m] = s + (add_c ? g_c : 0.f);
    }
}

// ---------------------------------------------------------------------------
// Shared wmma machinery (validated round 6, verbatim layout)
// ---------------------------------------------------------------------------
#define FTILE_E 40
#define FTILE_B (128 * 80)
#define FBUF_B  (4 * FTILE_B)
#define FBUFS   (2 * FBUF_B)          // 81920
#define FL_WS   FBUFS
#define FL_BT   (FBUFS + 512)
#define FLASH_SMEM (FBUFS + 1024)
#define STG_PITCH 132

typedef wmma::fragment<wmma::matrix_a, 16, 16, 16, __nv_bfloat16, wmma::row_major> FragA;
typedef wmma::fragment<wmma::matrix_b, 16, 16, 16, __nv_bfloat16, wmma::col_major> FragB;
typedef wmma::fragment<wmma::accumulator, 16, 16, 16, float> FragC;

__device__ __forceinline__ void load16(float* v, const float* p) {
#pragma unroll
    for (int i = 0; i < 4; ++i) ((float4*)v)[i] = ((const float4*)p)[i];
}

__device__ __forceinline__ void split16_store(char* hi, char* lo, uint32_t off,
                                              const float* v) {
    alignas(16) __nv_bfloat16 h[16], l[16];
#pragma unroll
    for (int j = 0; j < 16; ++j) {
        float f = v[j];
        __nv_bfloat16 hh = __float2bfloat16(f);
        h[j] = hh;
        l[j] = __float2bfloat16(f - __bfloat162float(hh));
    }
    *(uint4*)(hi + off)      = ((const uint4*)h)[0];
    *(uint4*)(hi + off + 16) = ((const uint4*)h)[1];
    *(uint4*)(lo + off)      = ((const uint4*)l)[0];
    *(uint4*)(lo + off + 16) = ((const uint4*)l)[1];
}

__device__ __forceinline__ void mma_chunk(const char* buf, int wm, int wn,
                                          FragC (&acc)[2][4])
{
    const __nv_bfloat16* tQ  = (const __nv_bfloat16*)(buf);
    const __nv_bfloat16* tQl = (const __nv_bfloat16*)(buf + FTILE_B);
    const __nv_bfloat16* tK  = (const __nv_bfloat16*)(buf + 2 * FTILE_B);
    const __nv_bfloat16* tKl = (const __nv_bfloat16*)(buf + 3 * FTILE_B);
#pragma unroll
    for (int ks = 0; ks < 2; ++ks) {
        FragA ah[2], al[2];
#pragma unroll
        for (int mi = 0; mi < 2; ++mi) {
            int ro = (32 * wm + 16 * mi) * FTILE_E + ks * 16;
            wmma::load_matrix_sync(ah[mi], tQ + ro, FTILE_E);
            wmma::load_matrix_sync(al[mi], tQl + ro, FTILE_E);
        }
#pragma unroll
        for (int p = 0; p < 4; ++p) {
            int ro = (64 * wn + 16 * p) * FTILE_E + ks * 16;
            FragB bh, bl;
            wmma::load_matrix_sync(bh, tK + ro, FTILE_E);
            wmma::load_matrix_sync(bl, tKl + ro, FTILE_E);
#pragma unroll
            for (int mi = 0; mi < 2; ++mi) {
                wmma::mma_sync(acc[mi][p], ah[mi], bh, acc[mi][p]);
                wmma::mma_sync(acc[mi][p], ah[mi], bl, acc[mi][p]);
                wmma::mma_sync(acc[mi][p], al[mi], bh, acc[mi][p]);
            }
        }
    }
}

// ---------------------------------------------------------------------------
// wmma A@B^T: C[m0+128, n0+128] = A[m0.., :] . B[n0.., :]^T  (3-split bf16)
// A, B row-major pitch Dd. grid (ncols/128, nrows/128), 256 threads.
// Mainloop identical to validated flash; epilogue = fp32 store.
// ---------------------------------------------------------------------------
__global__ void __launch_bounds__(256, 1)
wmma_abt(const float* __restrict__ A, const float* __restrict__ B,
         float* __restrict__ C)
{
    extern __shared__ char sm[];
    int tid = threadIdx.x;
    int wid = tid >> 5;
    int wm = wid & 3, wn = wid >> 2;
    int m0 = blockIdx.y * 128;
    int n0 = blockIdx.x * 128;

    float* stage = (float*)sm;

    int row = tid >> 1;
    int half = tid & 1;
    uint32_t soff = (uint32_t)row * 80 + half * 32;
    const float* arow = A + (size_t)(m0 + row) * Dd + half * 16;
    const float* brow = B + (size_t)(n0 + row) * Dd + half * 16;

    FragC acc[2][4];
#pragma unroll
    for (int mi = 0; mi < 2; ++mi)
#pragma unroll
        for (int p = 0; p < 4; ++p)
            wmma::fill_fragment(acc[mi][p], 0.f);

    float areg[16], breg[16];
    load16(areg, arow);
    load16(breg, brow);
    split16_store(sm, sm + FTILE_B, soff, areg);
    split16_store(sm + 2 * FTILE_B, sm + 3 * FTILE_B, soff, breg);
    __syncthreads();

    const int NK = Dd / 32;
    for (int kc = 0; kc < NK; ++kc) {
        char* buf = sm + (size_t)(kc & 1) * FBUF_B;
        bool pre = (kc + 1 < NK);
        if (pre) {
            load16(areg, arow + (kc + 1) * 32);
            load16(breg, brow + (kc + 1) * 32);
        }
        mma_chunk(buf, wm, wn, acc);
        if (pre) {
            char* nb = sm + (size_t)((kc + 1) & 1) * FBUF_B;
            split16_store(nb, nb + FTILE_B, soff, areg);
            split16_store(nb + 2 * FTILE_B, nb + 3 * FTILE_B, soff, breg);
        }
        __syncthreads();
    }

    // stage fp32 result (buffers dead) and write out
#pragma unroll
    for (int mi = 0; mi < 2; ++mi)
#pragma unroll
        for (int p = 0; p < 4; ++p)
            wmma::store_matrix_sync(
                stage + (size_t)(32 * wm + 16 * mi) * STG_PITCH + 64 * wn + 16 * p,
                acc[mi][p], STG_PITCH, wmma::mem_row_major);
    __syncthreads();

    int r = tid >> 1;
    int c0 = (tid & 1) * 64;
    const float* srow = stage + (size_t)r * STG_PITCH + c0;
    float* crow = C + (size_t)(m0 + r) * Dd + n0 + c0;
#pragma unroll
    for (int j = 0; j < 16; ++j)
        ((float4*)crow)[j] = ((const float4*)srow)[j];
}

// ---------------------------------------------------------------------------
// wmma flash (validated round 6; diffs: B side = raw x, + per-column bt bias)
// scores = y . x^T + bt ; softmax ; rank-1 w reduction.
// grid (Ss/128, Bb), 256 threads.
// ---------------------------------------------------------------------------
__global__ void __launch_bounds__(256, 1)
wmma_flash(const float* __restrict__ x, const float* __restrict__ bo,
           float* __restrict__ out)
{
    extern __shared__ char sm[];
    int tid = threadIdx.x;
    int wid = tid >> 5;
    int wm = wid & 3, wn = wid >> 2;
    int b = blockIdx.y;
    int q0 = blockIdx.x * 128;

    float* ws  = (float*)(sm + FL_WS);
    float* bts = (float*)(sm + FL_BT);
    float* stage = (float*)sm;

    const float* qb = g_y + ((size_t)b * Ss + q0) * Dd;
    const float* kb = x + (size_t)b * Ss * Dd;
    const float bo0 = __ldg(bo);

    int row = tid >> 1;
    int half = tid & 1;
    uint32_t soff = (uint32_t)row * 80 + half * 32;
    const float* qrow = qb + (size_t)row * Dd + half * 16;

    const int NK = Dd / 32;
    float rm = -1e30f, rl = 0.f, rc = 0.f;

    for (int t0 = 0; t0 < Ss; t0 += 128) {
        const float* krow = kb + (size_t)(t0 + row) * Dd + half * 16;
        if (tid < 128) {
            ws[tid]  = g_w[(size_t)b * Ss + t0 + tid];
            bts[tid] = g_bt[(size_t)b * Ss + t0 + tid];
        }

        FragC acc[2][4];
#pragma unroll
        for (int mi = 0; mi < 2; ++mi)
#pragma unroll
            for (int p = 0; p < 4; ++p)
                wmma::fill_fragment(acc[mi][p], 0.f);

        float qreg[16], kreg[16];
        load16(qreg, qrow);
        load16(kreg, krow);
        split16_store(sm, sm + FTILE_B, soff, qreg);
        split16_store(sm + 2 * FTILE_B, sm + 3 * FTILE_B, soff, kreg);
        __syncthreads();

        for (int kc = 0; kc < NK; ++kc) {
            char* buf = sm + (size_t)(kc & 1) * FBUF_B;
            bool pre = (kc + 1 < NK);
            if (pre) {
                load16(qreg, qrow + (kc + 1) * 32);
                load16(kreg, krow + (kc + 1) * 32);
            }
            mma_chunk(buf, wm, wn, acc);
            if (pre) {
                char* nb = sm + (size_t)((kc + 1) & 1) * FBUF_B;
                split16_store(nb, nb + FTILE_B, soff, qreg);
                split16_store(nb + 2 * FTILE_B, nb + 3 * FTILE_B, soff, kreg);
            }
            __syncthreads();
        }

#pragma unroll
        for (int mi = 0; mi < 2; ++mi)
#pragma unroll
            for (int p = 0; p < 4; ++p)
                wmma::store_matrix_sync(
                    stage + (size_t)(32 * wm + 16 * mi) * STG_PITCH + 64 * wn + 16 * p,
                    acc[mi][p], STG_PITCH, wmma::mem_row_major);
        __syncthreads();

        if (tid < 128) {
            const float4* rp = (const float4*)(stage + (size_t)tid * STG_PITCH);
            const float4* btp = (const float4*)bts;
            float m = -1e30f;
#pragma unroll 8
            for (int j = 0; j < 32; ++j) {
                float4 s4 = rp[j];
                float4 b4 = btp[j];
                s4.x += b4.x; s4.y += b4.y; s4.z += b4.z; s4.w += b4.w;
                m = fmaxf(m, fmaxf(fmaxf(s4.x, s4.y), fmaxf(s4.z, s4.w)));
            }
            float nm = fmaxf(rm, m);
            float f = __expf(rm - nm);
            float tl = 0.f, ta = 0.f;
            const float4* wp = (const float4*)ws;
#pragma unroll 8
            for (int j = 0; j < 32; ++j) {
                float4 s4 = rp[j];
                float4 b4 = btp[j];
                float4 w4 = wp[j];
                float p0 = __expf(s4.x + b4.x - nm);
                float p1 = __expf(s4.y + b4.y - nm);
                float p2 = __expf(s4.z + b4.z - nm);
                float p3 = __expf(s4.w + b4.w - nm);
                tl += (p0 + p1) + (p2 + p3);
                ta += p0 * w4.x + p1 * w4.y + p2 * w4.z + p3 * w4.w;
            }
            rl = rl * f + tl;
            rc = rc * f + ta;
            rm = nm;
        }
        __syncthreads();
    }

    if (tid < 128)
        out[(size_t)b * Ss + q0 + tid] = rc / rl + bo0;
}

// ---------------------------------------------------------------------------
extern "C" void kernel_launch(void* const* d_in, const int* in_sizes, int n_in,
                              void* d_out, int out_size)
{
    const float* x  = (const float*)d_in[0];
    const float* Wq = (const float*)d_in[1];
    const float* bq = (const float*)d_in[2];
    const float* Wk = (const float*)d_in[3];
    const float* bk = (const float*)d_in[4];
    const float* Wv = (const float*)d_in[5];
    const float* bv = (const float*)d_in[6];
    const float* Wo = (const float*)d_in[7];
    const float* bo = (const float*)d_in[8];
    float* out = (float*)d_out;
    (void)bk; (void)in_sizes; (void)n_in; (void)out_size;

    static bool attr_done = false;
    if (!attr_done) {
        cudaFuncSetAttribute(wmma_abt,
                             cudaFuncAttributeMaxDynamicSharedMemorySize, FLASH_SMEM);
        cudaFuncSetAttribute(wmma_flash,
                             cudaFuncAttributeMaxDynamicSharedMemorySize, FLASH_SMEM);
        attr_done = true;
    }

    float* yq = nullptr; cudaGetSymbolAddress((void**)&yq, g_y);
    float* mt = nullptr; cudaGetSymbolAddress((void**)&mt, g_mt);
    float* uu = nullptr; cudaGetSymbolAddress((void**)&uu, g_u);
    float* hh = nullptr; cudaGetSymbolAddress((void**)&hh, g_h);
    float* ww = nullptr; cudaGetSymbolAddress((void**)&ww, g_w);
    float* bt = nullptr; cudaGetSymbolAddress((void**)&bt, g_bt);

    // value path: u = Wv@Wo, c = bv.Wo, w = x@u + c
    prep_dot<<<Dd / 256, 256>>>(Wv, Wo, uu);
    prep_c<<<1, 256>>>(bv, Wo);
    gemv_row<<<Mtot, 256>>>(x, uu, ww, 1);

    // score column bias: h = Wk@bq, bt = x@h
    prep_dot<<<Dd / 256, 256>>>(Wk, bq, hh);
    gemv_row<<<Mtot, 256>>>(x, hh, bt, 0);

    // Mt = Wk @ Wq^T  (so y = x @ Mt^T), then y = x @ Mt^T
    {
        dim3 gm(Dd / 128, Dd / 128);
        wmma_abt<<<gm, 256, FLASH_SMEM>>>(Wk, Wq, mt);
        dim3 gy(Dd / 128, Mtot / 128);
        wmma_abt<<<gy, 256, FLASH_SMEM>>>(x, mt, yq);
    }

    // fused scores(y.x^T + bt) + softmax + rank-1 w reduction
    dim3 gf(Ss / 128, Bb);
    wmma_flash<<<gf, 256, FLASH_SMEM>>>(x, bo, out);
}

// round 8
// speedup vs baseline: 2.6925x; 1.1493x over previous
#include <cuda_runtime.h>
#include <cuda_bf16.h>
#include <mma.h>
#include <cstdint>

using namespace nvcuda;

#define Bb 8
#define Ss 2048
#define Dd 1024
#define Mtot (Bb * Ss)

// ---------------------------------------------------------------------------
// Device-global scratch
// ---------------------------------------------------------------------------
__device__ float g_y[(size_t)Mtot * Dd];   // y = x @ Mt^T
__device__ float g_mt[(size_t)Dd * Dd];    // Mt = Wk @ Wq^T
__device__ float g_w[Mtot];                // v_t . Wo per token
__device__ float g_bt[Mtot];               // x_t . (Wk bq)
__device__ float g_u[Dd];                  // Wv @ Wo
__device__ float g_h[Dd];                  // Wk @ bq
__device__ float g_c;                      // bv . Wo

// ---------------------------------------------------------------------------
// prep kernels
// ---------------------------------------------------------------------------
__global__ void prep_c(const float* __restrict__ bv, const float* __restrict__ Wo)
{
    __shared__ float red[8];
    int tid = threadIdx.x;
    float4 a = ((const float4*)bv)[tid];
    float4 b = ((const float4*)Wo)[tid];
    float s = a.x * b.x + a.y * b.y + a.z * b.z + a.w * b.w;
    #pragma unroll
    for (int off = 16; off; off >>= 1) s += __shfl_xor_sync(0xffffffffu, s, off);
    if ((tid & 31) == 0) red[tid >> 5] = s;
    __syncthreads();
    if (tid < 8) {
        s = red[tid];
        #pragma unroll
        for (int off = 4; off; off >>= 1) s += __shfl_xor_sync(0xffu, s, off);
        if (tid == 0) g_c = s;
    }
}

// one block per row: out[m] = row(A,m) . vec
__global__ void gemv_row(const float* __restrict__ A, const float* __restrict__ vec,
                         float* __restrict__ outv)
{
    __shared__ float red[8];
    int m = blockIdx.x;
    int tid = threadIdx.x;
    float4 a = ((const float4*)(A + (size_t)m * Dd))[tid];
    float4 u = ((const float4*)vec)[tid];
    float s = a.x * u.x + a.y * u.y + a.z * u.z + a.w * u.w;
    #pragma unroll
    for (int off = 16; off; off >>= 1) s += __shfl_xor_sync(0xffffffffu, s, off);
    if ((tid & 31) == 0) red[tid >> 5] = s;
    __syncthreads();
    if (tid < 8) {
        s = red[tid];
        #pragma unroll
        for (int off = 4; off; off >>= 1) s += __shfl_xor_sync(0xffu, s, off);
        if (tid == 0) outv[m] = s;
    }
}

// fused: w[m] = x_m.u + c ; bt[m] = x_m.h   (x row loaded once)
__global__ void gemv_row2(const float* __restrict__ x)
{
    __shared__ float red1[8], red2[8];
    int m = blockIdx.x;
    int tid = threadIdx.x;
    float4 a = ((const float4*)(x + (size_t)m * Dd))[tid];
    float4 u = ((const float4*)g_u)[tid];
    float4 h = ((const float4*)g_h)[tid];
    float s1 = a.x * u.x + a.y * u.y + a.z * u.z + a.w * u.w;
    float s2 = a.x * h.x + a.y * h.y + a.z * h.z + a.w * h.w;
    #pragma unroll
    for (int off = 16; off; off >>= 1) {
        s1 += __shfl_xor_sync(0xffffffffu, s1, off);
        s2 += __shfl_xor_sync(0xffffffffu, s2, off);
    }
    if ((tid & 31) == 0) { red1[tid >> 5] = s1; red2[tid >> 5] = s2; }
    __syncthreads();
    if (tid < 8) {
        s1 = red1[tid]; s2 = red2[tid];
        #pragma unroll
        for (int off = 4; off; off >>= 1) {
            s1 += __shfl_xor_sync(0xffu, s1, off);
            s2 += __shfl_xor_sync(0xffu, s2, off);
        }
        if (tid == 0) { g_w[m] = s1 + g_c; g_bt[m] = s2; }
    }
}

// ---------------------------------------------------------------------------
// Shared wmma machinery (validated layout; warp tile now 32x32, 16 warps)
// ---------------------------------------------------------------------------
#define FTILE_E 40
#define FTILE_B (128 * 80)
#define FBUF_B  (4 * FTILE_B)
#define FBUFS   (2 * FBUF_B)          // 81920
#define FL_WS   FBUFS
#define FL_BT   (FBUFS + 512)
#define FLASH_SMEM (FBUFS + 1024)
#define STG_PITCH 132

typedef wmma::fragment<wmma::matrix_a, 16, 16, 16, __nv_bfloat16, wmma::row_major> FragA;
typedef wmma::fragment<wmma::matrix_b, 16, 16, 16, __nv_bfloat16, wmma::col_major> FragB;
typedef wmma::fragment<wmma::accumulator, 16, 16, 16, float> FragC;

__device__ __forceinline__ void load16(float* v, const float* p) {
#pragma unroll
    for (int i = 0; i < 4; ++i) ((float4*)v)[i] = ((const float4*)p)[i];
}

__device__ __forceinline__ void split16_store(char* hi, char* lo, uint32_t off,
                                              const float* v) {
    alignas(16) __nv_bfloat16 h[16], l[16];
#pragma unroll
    for (int j = 0; j < 16; ++j) {
        float f = v[j];
        __nv_bfloat16 hh = __float2bfloat16(f);
        h[j] = hh;
        l[j] = __float2bfloat16(f - __bfloat162float(hh));
    }
    *(uint4*)(hi + off)      = ((const uint4*)h)[0];
    *(uint4*)(hi + off + 16) = ((const uint4*)h)[1];
    *(uint4*)(lo + off)      = ((const uint4*)l)[0];
    *(uint4*)(lo + off + 16) = ((const uint4*)l)[1];
}

// One 32-k chunk, 3-split, warp tile 32(m) x 32(n). wm, wn in 0..3.
__device__ __forceinline__ void mma_chunk32(const char* buf, int wm, int wn,
                                            FragC (&acc)[2][2])
{
    const __nv_bfloat16* tQ  = (const __nv_bfloat16*)(buf);
    const __nv_bfloat16* tQl = (const __nv_bfloat16*)(buf + FTILE_B);
    const __nv_bfloat16* tK  = (const __nv_bfloat16*)(buf + 2 * FTILE_B);
    const __nv_bfloat16* tKl = (const __nv_bfloat16*)(buf + 3 * FTILE_B);
#pragma unroll
    for (int ks = 0; ks < 2; ++ks) {
        FragA ah[2], al[2];
#pragma unroll
        for (int mi = 0; mi < 2; ++mi) {
            int ro = (32 * wm + 16 * mi) * FTILE_E + ks * 16;
            wmma::load_matrix_sync(ah[mi], tQ + ro, FTILE_E);
            wmma::load_matrix_sync(al[mi], tQl + ro, FTILE_E);
        }
#pragma unroll
        for (int pj = 0; pj < 2; ++pj) {
            int ro = (32 * wn + 16 * pj) * FTILE_E + ks * 16;
            FragB bh, bl;
            wmma::load_matrix_sync(bh, tK + ro, FTILE_E);
            wmma::load_matrix_sync(bl, tKl + ro, FTILE_E);
#pragma unroll
            for (int mi = 0; mi < 2; ++mi) {
                wmma::mma_sync(acc[mi][pj], ah[mi], bh, acc[mi][pj]);
                wmma::mma_sync(acc[mi][pj], ah[mi], bl, acc[mi][pj]);
                wmma::mma_sync(acc[mi][pj], al[mi], bh, acc[mi][pj]);
            }
        }
    }
}

// ---------------------------------------------------------------------------
// wmma A@B^T: C[m0+128, n0+128] = A[m0..,:] . B[n0..,:]^T  (512 threads)
// ---------------------------------------------------------------------------
__global__ void __launch_bounds__(512, 1)
wmma_abt(const float* __restrict__ A, const float* __restrict__ B,
         float* __restrict__ C)
{
    extern __shared__ char sm[];
    int tid = threadIdx.x;
    int wid = tid >> 5;
    int wm = wid & 3, wn = wid >> 2;
    int m0 = blockIdx.y * 128;
    int n0 = blockIdx.x * 128;

    float* stage = (float*)sm;

    int side = tid >> 8;            // 0: A tiles, 1: B tiles
    int t2 = tid & 255;
    int row = t2 >> 1;
    int half = t2 & 1;
    uint32_t soff = (uint32_t)row * 80 + half * 32;
    uint32_t tbase = side ? 2 * FTILE_B : 0;
    const float* srow = (side ? B + (size_t)(n0 + row) * Dd
                              : A + (size_t)(m0 + row) * Dd) + half * 16;

    FragC acc[2][2];
#pragma unroll
    for (int mi = 0; mi < 2; ++mi)
#pragma unroll
        for (int pj = 0; pj < 2; ++pj)
            wmma::fill_fragment(acc[mi][pj], 0.f);

    float reg[16];
    load16(reg, srow);
    split16_store(sm + tbase, sm + tbase + FTILE_B, soff, reg);
    __syncthreads();

    const int NK = Dd / 32;
    for (int kc = 0; kc < NK; ++kc) {
        char* buf = sm + (size_t)(kc & 1) * FBUF_B;
        bool pre = (kc + 1 < NK);
        if (pre) load16(reg, srow + (kc + 1) * 32);
        mma_chunk32(buf, wm, wn, acc);
        if (pre) {
            char* nb = sm + (size_t)((kc + 1) & 1) * FBUF_B;
            split16_store(nb + tbase, nb + tbase + FTILE_B, soff, reg);
        }
        __syncthreads();
    }

#pragma unroll
    for (int mi = 0; mi < 2; ++mi)
#pragma unroll
        for (int pj = 0; pj < 2; ++pj)
            wmma::store_matrix_sync(
                stage + (size_t)(32 * wm + 16 * mi) * STG_PITCH + 32 * wn + 16 * pj,
                acc[mi][pj], STG_PITCH, wmma::mem_row_major);
    __syncthreads();

    int r = tid >> 2;
    int c0 = (tid & 3) * 32;
    const float* sr = stage + (size_t)r * STG_PITCH + c0;
    float* cr = C + (size_t)(m0 + r) * Dd + n0 + c0;
#pragma unroll
    for (int j = 0; j < 8; ++j)
        ((float4*)cr)[j] = ((const float4*)sr)[j];
}

// ---------------------------------------------------------------------------
// wmma flash: scores = y . x^T + bt ; softmax ; rank-1 w. (512 threads)
// grid (Ss/128, Bb).
// ---------------------------------------------------------------------------
__global__ void __launch_bounds__(512, 1)
wmma_flash(const float* __restrict__ x, const float* __restrict__ bo,
           float* __restrict__ out)
{
    extern __shared__ char sm[];
    int tid = threadIdx.x;
    int wid = tid >> 5;
    int wm = wid & 3, wn = wid >> 2;
    int b = blockIdx.y;
    int q0 = blockIdx.x * 128;

    float* ws  = (float*)(sm + FL_WS);
    float* bts = (float*)(sm + FL_BT);
    float* stage = (float*)sm;

    const float* qb = g_y + ((size_t)b * Ss + q0) * Dd;
    const float* kb = x + (size_t)b * Ss * Dd;
    const float bo0 = __ldg(bo);

    int side = tid >> 8;            // 0: q tiles, 1: k tiles
    int t2 = tid & 255;
    int row = t2 >> 1;
    int half = t2 & 1;
    uint32_t soff = (uint32_t)row * 80 + half * 32;
    uint32_t tbase = side ? 2 * FTILE_B : 0;
    const float* qrow = qb + (size_t)row * Dd + half * 16;

    const int NK = Dd / 32;
    float rm = -1e30f, rl = 0.f, rc = 0.f;      // row = tid (<128)

    for (int t0 = 0; t0 < Ss; t0 += 128) {
        const float* srow = side ? kb + (size_t)(t0 + row) * Dd + half * 16 : qrow;
        if (tid < 128) {
            ws[tid]  = g_w[(size_t)b * Ss + t0 + tid];
            bts[tid] = g_bt[(size_t)b * Ss + t0 + tid];
        }

        FragC acc[2][2];
#pragma unroll
        for (int mi = 0; mi < 2; ++mi)
#pragma unroll
            for (int pj = 0; pj < 2; ++pj)
                wmma::fill_fragment(acc[mi][pj], 0.f);

        float reg[16];
        load16(reg, srow);
        split16_store(sm + tbase, sm + tbase + FTILE_B, soff, reg);
        __syncthreads();

        for (int kc = 0; kc < NK; ++kc) {
            char* buf = sm + (size_t)(kc & 1) * FBUF_B;
            bool pre = (kc + 1 < NK);
            if (pre) load16(reg, srow + (kc + 1) * 32);
            mma_chunk32(buf, wm, wn, acc);
            if (pre) {
                char* nb = sm + (size_t)((kc + 1) & 1) * FBUF_B;
                split16_store(nb + tbase, nb + tbase + FTILE_B, soff, reg);
            }
            __syncthreads();
        }

#pragma unroll
        for (int mi = 0; mi < 2; ++mi)
#pragma unroll
            for (int pj = 0; pj < 2; ++pj)
                wmma::store_matrix_sync(
                    stage + (size_t)(32 * wm + 16 * mi) * STG_PITCH + 32 * wn + 16 * pj,
                    acc[mi][pj], STG_PITCH, wmma::mem_row_major);
        __syncthreads();

        if (tid < 128) {
            const float4* rp = (const float4*)(stage + (size_t)tid * STG_PITCH);
            const float4* btp = (const float4*)bts;
            float m = -1e30f;
#pragma unroll 8
            for (int j = 0; j < 32; ++j) {
                float4 s4 = rp[j];
                float4 b4 = btp[j];
                s4.x += b4.x; s4.y += b4.y; s4.z += b4.z; s4.w += b4.w;
                m = fmaxf(m, fmaxf(fmaxf(s4.x, s4.y), fmaxf(s4.z, s4.w)));
            }
            float nm = fmaxf(rm, m);
            float f = __expf(rm - nm);
            float tl = 0.f, ta = 0.f;
            const float4* wp = (const float4*)ws;
#pragma unroll 8
            for (int j = 0; j < 32; ++j) {
                float4 s4 = rp[j];
                float4 b4 = btp[j];
                float4 w4 = wp[j];
                float p0 = __expf(s4.x + b4.x - nm);
                float p1 = __expf(s4.y + b4.y - nm);
                float p2 = __expf(s4.z + b4.z - nm);
                float p3 = __expf(s4.w + b4.w - nm);
                tl += (p0 + p1) + (p2 + p3);
                ta += p0 * w4.x + p1 * w4.y + p2 * w4.z + p3 * w4.w;
            }
            rl = rl * f + tl;
            rc = rc * f + ta;
            rm = nm;
        }
        __syncthreads();
    }

    if (tid < 128)
        out[(size_t)b * Ss + q0 + tid] = rc / rl + bo0;
}

// ---------------------------------------------------------------------------
extern "C" void kernel_launch(void* const* d_in, const int* in_sizes, int n_in,
                              void* d_out, int out_size)
{
    const float* x  = (const float*)d_in[0];
    const float* Wq = (const float*)d_in[1];
    const float* bq = (const float*)d_in[2];
    const float* Wk = (const float*)d_in[3];
    const float* bk = (const float*)d_in[4];
    const float* Wv = (const float*)d_in[5];
    const float* bv = (const float*)d_in[6];
    const float* Wo = (const float*)d_in[7];
    const float* bo = (const float*)d_in[8];
    float* out = (float*)d_out;
    (void)bk; (void)in_sizes; (void)n_in; (void)out_size;

    static bool attr_done = false;
    if (!attr_done) {
        cudaFuncSetAttribute(wmma_abt,
                             cudaFuncAttributeMaxDynamicSharedMemorySize, FLASH_SMEM);
        cudaFuncSetAttribute(wmma_flash,
                             cudaFuncAttributeMaxDynamicSharedMemorySize, FLASH_SMEM);
        attr_done = true;
    }

    float* yq = nullptr; cudaGetSymbolAddress((void**)&yq, g_y);
    float* mt = nullptr; cudaGetSymbolAddress((void**)&mt, g_mt);
    float* uu = nullptr; cudaGetSymbolAddress((void**)&uu, g_u);
    float* hh = nullptr; cudaGetSymbolAddress((void**)&hh, g_h);

    // scalars + per-feature vectors
    prep_c<<<1, 256>>>(bv, Wo);
    gemv_row<<<Dd, 256>>>(Wv, Wo, uu);    // u = Wv @ Wo
    gemv_row<<<Dd, 256>>>(Wk, bq, hh);    // h = Wk @ bq
    gemv_row2<<<Mtot, 256>>>(x);          // w = x.u + c ; bt = x.h

    // Mt = Wk @ Wq^T, then y = x @ Mt^T
    {
        dim3 gm(Dd / 128, Dd / 128);
        wmma_abt<<<gm, 512, FLASH_SMEM>>>(Wk, Wq, mt);
        dim3 gy(Dd / 128, Mtot / 128);
        wmma_abt<<<gy, 512, FLASH_SMEM>>>(x, mt, yq);
    }

    // fused scores(y.x^T + bt) + softmax + rank-1 w reduction
    dim3 gf(Ss / 128, Bb);
    wmma_flash<<<gf, 512, FLASH_SMEM>>>(x, bo, out);
}